// round 3
// baseline (speedup 1.0000x reference)
#include <cuda_runtime.h>
#include <math.h>

// Problem constants (B=2, H=16, S=2048, D=64, fp32)
#define Bb 2
#define Hh 16
#define Ss 2048
#define Dd 64
#define BM 64
#define BN 64
#define STRIDE 68          // padded smem row stride (floats), keeps 16B alignment
#define NTHREADS 128

#define SMEM_FLOATS (4 * BM * STRIDE)      // sQ, sK, sV, sP
#define SMEM_BYTES  (SMEM_FLOATS * 4)

__global__ __launch_bounds__(NTHREADS) void attn_kernel(
    const float* __restrict__ q,
    const float* __restrict__ k,
    const float* __restrict__ v,
    const float* __restrict__ key_mask,     // [B, S]
    const float* __restrict__ scale_factor, // [B]
    float* __restrict__ out)
{
    extern __shared__ float smem[];
    float* sQ = smem;
    float* sK = smem + BM * STRIDE;
    float* sV = smem + 2 * BM * STRIDE;
    float* sP = smem + 3 * BM * STRIDE;

    const int qt = blockIdx.x;   // query tile 0..31
    const int bh = blockIdx.y;   // 0..31
    const int b  = bh / Hh;
    const float scale = scale_factor[b];
    const float* km = key_mask + (size_t)b * Ss;

    const float* qb = q + ((size_t)bh * Ss + (size_t)qt * BM) * Dd;
    const float* kb = k + (size_t)bh * Ss * Dd;
    const float* vb = v + (size_t)bh * Ss * Dd;
    float* ob = out + ((size_t)bh * Ss + (size_t)qt * BM) * Dd;

    const int tid = threadIdx.x;

    // Load Q tile (64x64), pre-scaled by scale_factor.
    for (int i = tid; i < BM * (Dd / 4); i += NTHREADS) {
        int r = i / (Dd / 4);
        int c = i % (Dd / 4);
        float4 val = ((const float4*)qb)[r * (Dd / 4) + c];
        val.x *= scale; val.y *= scale; val.z *= scale; val.w *= scale;
        *(float4*)&sQ[r * STRIDE + c * 4] = val;
    }

    const int tr = tid >> 3;       // 0..15: owns 4 rows
    const int tc = tid & 7;        // 0..7 : owns 8 cols
    const int row0 = tr * 4;
    const int col0 = tc * 8;

    float m_i[4], l_i[4];
    float acc[4][8];
    #pragma unroll
    for (int i = 0; i < 4; i++) {
        m_i[i] = -INFINITY;
        l_i[i] = 0.f;
        #pragma unroll
        for (int j = 0; j < 8; j++) acc[i][j] = 0.f;
    }

    for (int kt = 0; kt < Ss / BN; kt++) {
        __syncthreads();   // previous tile's sP/sV reads done (and Q load on kt=0)

        // Load K and V tiles (64x64 each)
        const float* kp = kb + (size_t)kt * BN * Dd;
        const float* vp = vb + (size_t)kt * BN * Dd;
        for (int i = tid; i < BN * (Dd / 4); i += NTHREADS) {
            int r = i / (Dd / 4);
            int c = i % (Dd / 4);
            *(float4*)&sK[r * STRIDE + c * 4] = ((const float4*)kp)[r * (Dd / 4) + c];
            *(float4*)&sV[r * STRIDE + c * 4] = ((const float4*)vp)[r * (Dd / 4) + c];
        }
        __syncthreads();

        // ---- S = (Q*scale) @ K^T  (4x8 fragment per thread) ----
        float s[4][8];
        #pragma unroll
        for (int i = 0; i < 4; i++)
            #pragma unroll
            for (int j = 0; j < 8; j++) s[i][j] = 0.f;

        #pragma unroll 2
        for (int d4 = 0; d4 < Dd / 4; d4++) {
            float4 qv[4], kv[8];
            #pragma unroll
            for (int i = 0; i < 4; i++)
                qv[i] = *(const float4*)&sQ[(row0 + i) * STRIDE + d4 * 4];
            #pragma unroll
            for (int j = 0; j < 8; j++)
                kv[j] = *(const float4*)&sK[(col0 + j) * STRIDE + d4 * 4];
            #pragma unroll
            for (int i = 0; i < 4; i++)
                #pragma unroll
                for (int j = 0; j < 8; j++) {
                    s[i][j] = fmaf(qv[i].x, kv[j].x, s[i][j]);
                    s[i][j] = fmaf(qv[i].y, kv[j].y, s[i][j]);
                    s[i][j] = fmaf(qv[i].z, kv[j].z, s[i][j]);
                    s[i][j] = fmaf(qv[i].w, kv[j].w, s[i][j]);
                }
        }

        // key_mask values for this thread's 8 columns (post-softmax mask)
        float kmv[8];
        {
            const float4 a = *(const float4*)&km[kt * BN + col0];
            const float4 c = *(const float4*)&km[kt * BN + col0 + 4];
            kmv[0] = a.x; kmv[1] = a.y; kmv[2] = a.z; kmv[3] = a.w;
            kmv[4] = c.x; kmv[5] = c.y; kmv[6] = c.z; kmv[7] = c.w;
        }

        // ---- online softmax; denominator is UNMASKED, numerator uses mask ----
        #pragma unroll
        for (int i = 0; i < 4; i++) {
            float mloc = s[i][0];
            #pragma unroll
            for (int j = 1; j < 8; j++) mloc = fmaxf(mloc, s[i][j]);
            mloc = fmaxf(mloc, __shfl_xor_sync(0xffffffffu, mloc, 1));
            mloc = fmaxf(mloc, __shfl_xor_sync(0xffffffffu, mloc, 2));
            mloc = fmaxf(mloc, __shfl_xor_sync(0xffffffffu, mloc, 4));

            float mnew = fmaxf(m_i[i], mloc);
            float alpha = __expf(m_i[i] - mnew);   // exp(-inf)=0 on first tile
            m_i[i] = mnew;

            float lsum = 0.f;
            #pragma unroll
            for (int j = 0; j < 8; j++) {
                float p = __expf(s[i][j] - mnew);
                s[i][j] = p;
                lsum += p;
            }
            lsum += __shfl_xor_sync(0xffffffffu, lsum, 1);
            lsum += __shfl_xor_sync(0xffffffffu, lsum, 2);
            lsum += __shfl_xor_sync(0xffffffffu, lsum, 4);
            l_i[i] = l_i[i] * alpha + lsum;

            #pragma unroll
            for (int j = 0; j < 8; j++) acc[i][j] *= alpha;

            // store masked probabilities for the PV matmul
            #pragma unroll
            for (int j = 0; j < 8; j++)
                sP[(row0 + i) * STRIDE + col0 + j] = s[i][j] * kmv[j];
        }
        __syncthreads();

        // ---- acc += P_masked @ V ----
        #pragma unroll 2
        for (int kk = 0; kk < BN; kk += 4) {
            float4 pv[4];
            #pragma unroll
            for (int i = 0; i < 4; i++)
                pv[i] = *(const float4*)&sP[(row0 + i) * STRIDE + kk];
            #pragma unroll
            for (int u = 0; u < 4; u++) {
                const float4 va = *(const float4*)&sV[(kk + u) * STRIDE + col0];
                const float4 vb4 = *(const float4*)&sV[(kk + u) * STRIDE + col0 + 4];
                #pragma unroll
                for (int i = 0; i < 4; i++) {
                    const float p = ((const float*)&pv[i])[u];
                    acc[i][0] = fmaf(p, va.x,  acc[i][0]);
                    acc[i][1] = fmaf(p, va.y,  acc[i][1]);
                    acc[i][2] = fmaf(p, va.z,  acc[i][2]);
                    acc[i][3] = fmaf(p, va.w,  acc[i][3]);
                    acc[i][4] = fmaf(p, vb4.x, acc[i][4]);
                    acc[i][5] = fmaf(p, vb4.y, acc[i][5]);
                    acc[i][6] = fmaf(p, vb4.z, acc[i][6]);
                    acc[i][7] = fmaf(p, vb4.w, acc[i][7]);
                }
            }
        }
    }

    // ---- epilogue: divide by unmasked denominator, write out ----
    #pragma unroll
    for (int i = 0; i < 4; i++) {
        const float inv = 1.f / l_i[i];
        float4 o1, o2;
        o1.x = acc[i][0] * inv; o1.y = acc[i][1] * inv;
        o1.z = acc[i][2] * inv; o1.w = acc[i][3] * inv;
        o2.x = acc[i][4] * inv; o2.y = acc[i][5] * inv;
        o2.z = acc[i][6] * inv; o2.w = acc[i][7] * inv;
        *(float4*)&ob[(row0 + i) * Dd + col0]     = o1;
        *(float4*)&ob[(row0 + i) * Dd + col0 + 4] = o2;
    }
}

extern "C" void kernel_launch(void* const* d_in, const int* in_sizes, int n_in,
                              void* d_out, int out_size)
{
    const float* q  = (const float*)d_in[0];  // [B,H,S,D]
    const float* k  = (const float*)d_in[1];  // [B,H,S,D]
    const float* v  = (const float*)d_in[2];  // [B,H,S,D]
    // d_in[3] = query_mask (all ones, unused by reference math)
    const float* km = (const float*)d_in[4];  // [B,1,1,S]
    const float* sf = (const float*)d_in[5];  // [B,1,1,1]
    float* out = (float*)d_out;

    cudaFuncSetAttribute(attn_kernel,
                         cudaFuncAttributeMaxDynamicSharedMemorySize, SMEM_BYTES);

    dim3 grid(Ss / BM, Bb * Hh);   // 32 x 32
    attn_kernel<<<grid, NTHREADS, SMEM_BYTES>>>(q, k, v, km, sf, out);
}

// round 4
// speedup vs baseline: 2.8587x; 2.8587x over previous
#include <cuda_runtime.h>
#include <math.h>

// Problem constants (B=2, H=16, S=2048, D=64, fp32)
#define Bb 2
#define Hh 16
#define Ss 2048
#define Dd 64
#define BM 64
#define BN 64
#define STRIDE 68          // padded smem row stride (floats); 17 float4s per row (odd -> gap-1 rows conflict-free)
#define NTHREADS 128

#define SMEM_FLOATS (4 * BM * STRIDE + BN)   // sQ, sK, sV, sP, sM(mask tile)
#define SMEM_BYTES  (SMEM_FLOATS * 4)

__global__ __launch_bounds__(NTHREADS) void attn_kernel(
    const float* __restrict__ q,
    const float* __restrict__ k,
    const float* __restrict__ v,
    const float* __restrict__ key_mask,     // [B, S]
    const float* __restrict__ scale_factor, // [B]
    float* __restrict__ out)
{
    extern __shared__ float smem[];
    float* sQ = smem;
    float* sK = smem + BM * STRIDE;
    float* sV = smem + 2 * BM * STRIDE;
    float* sP = smem + 3 * BM * STRIDE;
    float* sM = smem + 4 * BM * STRIDE;   // 64 floats: key-mask tile

    const int qt = blockIdx.x;   // query tile 0..31
    const int bh = blockIdx.y;   // 0..31
    const int b  = bh / Hh;
    const float scale = scale_factor[b];
    const float* km = key_mask + (size_t)b * Ss;

    const float* qb = q + ((size_t)bh * Ss + (size_t)qt * BM) * Dd;
    const float* kb = k + (size_t)bh * Ss * Dd;
    const float* vb = v + (size_t)bh * Ss * Dd;
    float* ob = out + ((size_t)bh * Ss + (size_t)qt * BM) * Dd;

    const int tid = threadIdx.x;

    // Load Q tile (64x64), pre-scaled by scale_factor.
    for (int i = tid; i < BM * (Dd / 4); i += NTHREADS) {
        int r = i / (Dd / 4);
        int c = i % (Dd / 4);
        float4 val = ((const float4*)qb)[r * (Dd / 4) + c];
        val.x *= scale; val.y *= scale; val.z *= scale; val.w *= scale;
        *(float4*)&sQ[r * STRIDE + c * 4] = val;
    }

    // Thread fragment mapping (conflict-free LDS):
    //   rows owned:           r = tr + 16*i   (i = 0..3)   [both stages]
    //   S-stage cols owned:   c = tc + 8*j    (j = 0..7)   (scattered)
    //   PV-stage d cols:      d = tc*8 + j    (j = 0..7)   (contiguous float4s)
    const int tr = tid >> 3;       // 0..15
    const int tc = tid & 7;        // 0..7

    float m_i[4], l_i[4];
    float acc[4][8];
    #pragma unroll
    for (int i = 0; i < 4; i++) {
        m_i[i] = -INFINITY;
        l_i[i] = 0.f;
        #pragma unroll
        for (int j = 0; j < 8; j++) acc[i][j] = 0.f;
    }

    for (int kt = 0; kt < Ss / BN; kt++) {
        __syncthreads();   // previous tile's sP/sV reads done (and Q load on kt=0)

        // Load K and V tiles (64x64 each) + key-mask tile
        const float* kp = kb + (size_t)kt * BN * Dd;
        const float* vp = vb + (size_t)kt * BN * Dd;
        for (int i = tid; i < BN * (Dd / 4); i += NTHREADS) {
            int r = i / (Dd / 4);
            int c = i % (Dd / 4);
            *(float4*)&sK[r * STRIDE + c * 4] = ((const float4*)kp)[r * (Dd / 4) + c];
            *(float4*)&sV[r * STRIDE + c * 4] = ((const float4*)vp)[r * (Dd / 4) + c];
        }
        if (tid < BN / 4)
            *(float4*)&sM[tid * 4] = *(const float4*)&km[kt * BN + tid * 4];
        __syncthreads();

        // ---- S = (Q*scale) @ K^T  (4x8 scattered fragment per thread) ----
        float s[4][8];
        #pragma unroll
        for (int i = 0; i < 4; i++)
            #pragma unroll
            for (int j = 0; j < 8; j++) s[i][j] = 0.f;

        #pragma unroll 2
        for (int d4 = 0; d4 < Dd / 4; d4++) {
            float4 qv[4], kv[8];
            #pragma unroll
            for (int i = 0; i < 4; i++)
                qv[i] = *(const float4*)&sQ[(tr + 16 * i) * STRIDE + d4 * 4];   // lanes: gap-1 rows -> CF
            #pragma unroll
            for (int j = 0; j < 8; j++)
                kv[j] = *(const float4*)&sK[(tc + 8 * j) * STRIDE + d4 * 4];    // lanes: tc*17 mod 8 distinct -> CF
            #pragma unroll
            for (int i = 0; i < 4; i++)
                #pragma unroll
                for (int j = 0; j < 8; j++) {
                    s[i][j] = fmaf(qv[i].x, kv[j].x, s[i][j]);
                    s[i][j] = fmaf(qv[i].y, kv[j].y, s[i][j]);
                    s[i][j] = fmaf(qv[i].z, kv[j].z, s[i][j]);
                    s[i][j] = fmaf(qv[i].w, kv[j].w, s[i][j]);
                }
        }

        // key_mask values for this thread's 8 scattered columns (post-softmax mask)
        float kmv[8];
        #pragma unroll
        for (int j = 0; j < 8; j++) kmv[j] = sM[tc + 8 * j];

        // ---- online softmax; denominator is UNMASKED, numerator uses mask ----
        #pragma unroll
        for (int i = 0; i < 4; i++) {
            float mloc = s[i][0];
            #pragma unroll
            for (int j = 1; j < 8; j++) mloc = fmaxf(mloc, s[i][j]);
            mloc = fmaxf(mloc, __shfl_xor_sync(0xffffffffu, mloc, 1));
            mloc = fmaxf(mloc, __shfl_xor_sync(0xffffffffu, mloc, 2));
            mloc = fmaxf(mloc, __shfl_xor_sync(0xffffffffu, mloc, 4));

            float mnew = fmaxf(m_i[i], mloc);
            float alpha = __expf(m_i[i] - mnew);   // exp(-inf)=0 on first tile
            m_i[i] = mnew;

            float lsum = 0.f;
            #pragma unroll
            for (int j = 0; j < 8; j++) {
                float p = __expf(s[i][j] - mnew);
                s[i][j] = p;
                lsum += p;
            }
            lsum += __shfl_xor_sync(0xffffffffu, lsum, 1);
            lsum += __shfl_xor_sync(0xffffffffu, lsum, 2);
            lsum += __shfl_xor_sync(0xffffffffu, lsum, 4);
            l_i[i] = l_i[i] * alpha + lsum;

            #pragma unroll
            for (int j = 0; j < 8; j++) acc[i][j] *= alpha;

            // store masked probabilities for the PV matmul (scattered cols, <=2-way)
            #pragma unroll
            for (int j = 0; j < 8; j++)
                sP[(tr + 16 * i) * STRIDE + tc + 8 * j] = s[i][j] * kmv[j];
        }
        __syncthreads();

        // ---- acc += P_masked @ V  (contiguous d cols: d0 = tc*8) ----
        const int col0 = tc * 8;
        #pragma unroll 2
        for (int kk = 0; kk < BN; kk += 4) {
            float4 pv[4];
            #pragma unroll
            for (int i = 0; i < 4; i++)
                pv[i] = *(const float4*)&sP[(tr + 16 * i) * STRIDE + kk];       // lanes: gap-1 rows -> CF
            #pragma unroll
            for (int u = 0; u < 4; u++) {
                const float4 va  = *(const float4*)&sV[(kk + u) * STRIDE + col0];      // same-row distinct c4 -> CF
                const float4 vb4 = *(const float4*)&sV[(kk + u) * STRIDE + col0 + 4];
                #pragma unroll
                for (int i = 0; i < 4; i++) {
                    const float p = ((const float*)&pv[i])[u];
                    acc[i][0] = fmaf(p, va.x,  acc[i][0]);
                    acc[i][1] = fmaf(p, va.y,  acc[i][1]);
                    acc[i][2] = fmaf(p, va.z,  acc[i][2]);
                    acc[i][3] = fmaf(p, va.w,  acc[i][3]);
                    acc[i][4] = fmaf(p, vb4.x, acc[i][4]);
                    acc[i][5] = fmaf(p, vb4.y, acc[i][5]);
                    acc[i][6] = fmaf(p, vb4.z, acc[i][6]);
                    acc[i][7] = fmaf(p, vb4.w, acc[i][7]);
                }
            }
        }
    }

    // ---- epilogue: divide by unmasked denominator, write out ----
    const int col0 = tc * 8;
    #pragma unroll
    for (int i = 0; i < 4; i++) {
        const float inv = 1.f / l_i[i];
        float4 o1, o2;
        o1.x = acc[i][0] * inv; o1.y = acc[i][1] * inv;
        o1.z = acc[i][2] * inv; o1.w = acc[i][3] * inv;
        o2.x = acc[i][4] * inv; o2.y = acc[i][5] * inv;
        o2.z = acc[i][6] * inv; o2.w = acc[i][7] * inv;
        *(float4*)&ob[(tr + 16 * i) * Dd + col0]     = o1;
        *(float4*)&ob[(tr + 16 * i) * Dd + col0 + 4] = o2;
    }
}

extern "C" void kernel_launch(void* const* d_in, const int* in_sizes, int n_in,
                              void* d_out, int out_size)
{
    const float* q  = (const float*)d_in[0];  // [B,H,S,D]
    const float* k  = (const float*)d_in[1];  // [B,H,S,D]
    const float* v  = (const float*)d_in[2];  // [B,H,S,D]
    // d_in[3] = query_mask (all ones, unused by reference math)
    const float* km = (const float*)d_in[4];  // [B,1,1,S]
    const float* sf = (const float*)d_in[5];  // [B,1,1,1]
    float* out = (float*)d_out;

    cudaFuncSetAttribute(attn_kernel,
                         cudaFuncAttributeMaxDynamicSharedMemorySize, SMEM_BYTES);

    dim3 grid(Ss / BM, Bb * Hh);   // 32 x 32
    attn_kernel<<<grid, NTHREADS, SMEM_BYTES>>>(q, k, v, km, sf, out);
}

// round 5
// speedup vs baseline: 2.8633x; 1.0016x over previous
#include <cuda_runtime.h>
#include <math.h>

// Problem constants (B=2, H=16, S=2048, D=64, fp32)
#define Bb 2
#define Hh 16
#define Ss 2048
#define Dd 64
#define BM 64
#define BN 64
#define STRIDE 68          // padded smem row stride (floats); 17 float4s per row (odd -> gap-1 rows conflict-free)
#define NTHREADS 128

#define SMEM_FLOATS (4 * BM * STRIDE + BN)   // sQ, sK, sV, sP, sM(mask tile)
#define SMEM_BYTES  (SMEM_FLOATS * 4)

__global__ __launch_bounds__(NTHREADS) void attn_kernel(
    const float* __restrict__ q,
    const float* __restrict__ k,
    const float* __restrict__ v,
    const float* __restrict__ key_mask,     // [B, S]
    const float* __restrict__ scale_factor, // [B]
    float* __restrict__ out)
{
    extern __shared__ float smem[];
    float* sQ = smem;
    float* sK = smem + BM * STRIDE;
    float* sV = smem + 2 * BM * STRIDE;
    float* sP = smem + 3 * BM * STRIDE;
    float* sM = smem + 4 * BM * STRIDE;   // 64 floats: key-mask tile

    const int qt = blockIdx.x;   // query tile 0..31
    const int bh = blockIdx.y;   // 0..31
    const int b  = bh / Hh;
    const float scale = scale_factor[b];
    const float* km = key_mask + (size_t)b * Ss;

    const float* qb = q + ((size_t)bh * Ss + (size_t)qt * BM) * Dd;
    const float* kb = k + (size_t)bh * Ss * Dd;
    const float* vb = v + (size_t)bh * Ss * Dd;
    float* ob = out + ((size_t)bh * Ss + (size_t)qt * BM) * Dd;

    const int tid = threadIdx.x;

    // Load Q tile (64x64), pre-scaled by scale_factor.
    for (int i = tid; i < BM * (Dd / 4); i += NTHREADS) {
        int r = i / (Dd / 4);
        int c = i % (Dd / 4);
        float4 val = ((const float4*)qb)[r * (Dd / 4) + c];
        val.x *= scale; val.y *= scale; val.z *= scale; val.w *= scale;
        *(float4*)&sQ[r * STRIDE + c * 4] = val;
    }

    // Thread fragment mapping (conflict-free LDS):
    //   rows owned:           r = tr + 16*i   (i = 0..3)   [both stages]
    //   S-stage cols owned:   c = tc + 8*j    (j = 0..7)   (scattered)
    //   PV-stage d cols:      d = tc*8 + j    (j = 0..7)   (contiguous float4s)
    const int tr = tid >> 3;       // 0..15
    const int tc = tid & 7;        // 0..7

    float m_i[4], l_i[4];
    float acc[4][8];
    #pragma unroll
    for (int i = 0; i < 4; i++) {
        m_i[i] = -INFINITY;
        l_i[i] = 0.f;
        #pragma unroll
        for (int j = 0; j < 8; j++) acc[i][j] = 0.f;
    }

    for (int kt = 0; kt < Ss / BN; kt++) {
        __syncthreads();   // previous tile's sP/sV reads done (and Q load on kt=0)

        // Load K and V tiles (64x64 each) + key-mask tile
        const float* kp = kb + (size_t)kt * BN * Dd;
        const float* vp = vb + (size_t)kt * BN * Dd;
        for (int i = tid; i < BN * (Dd / 4); i += NTHREADS) {
            int r = i / (Dd / 4);
            int c = i % (Dd / 4);
            *(float4*)&sK[r * STRIDE + c * 4] = ((const float4*)kp)[r * (Dd / 4) + c];
            *(float4*)&sV[r * STRIDE + c * 4] = ((const float4*)vp)[r * (Dd / 4) + c];
        }
        if (tid < BN / 4)
            *(float4*)&sM[tid * 4] = *(const float4*)&km[kt * BN + tid * 4];
        __syncthreads();

        // ---- S = (Q*scale) @ K^T  (4x8 scattered fragment per thread) ----
        float s[4][8];
        #pragma unroll
        for (int i = 0; i < 4; i++)
            #pragma unroll
            for (int j = 0; j < 8; j++) s[i][j] = 0.f;

        #pragma unroll 2
        for (int d4 = 0; d4 < Dd / 4; d4++) {
            float4 qv[4], kv[8];
            #pragma unroll
            for (int i = 0; i < 4; i++)
                qv[i] = *(const float4*)&sQ[(tr + 16 * i) * STRIDE + d4 * 4];   // lanes: gap-1 rows -> CF
            #pragma unroll
            for (int j = 0; j < 8; j++)
                kv[j] = *(const float4*)&sK[(tc + 8 * j) * STRIDE + d4 * 4];    // lanes: tc*17 mod 8 distinct -> CF
            #pragma unroll
            for (int i = 0; i < 4; i++)
                #pragma unroll
                for (int j = 0; j < 8; j++) {
                    s[i][j] = fmaf(qv[i].x, kv[j].x, s[i][j]);
                    s[i][j] = fmaf(qv[i].y, kv[j].y, s[i][j]);
                    s[i][j] = fmaf(qv[i].z, kv[j].z, s[i][j]);
                    s[i][j] = fmaf(qv[i].w, kv[j].w, s[i][j]);
                }
        }

        // key_mask values for this thread's 8 scattered columns (post-softmax mask)
        float kmv[8];
        #pragma unroll
        for (int j = 0; j < 8; j++) kmv[j] = sM[tc + 8 * j];

        // ---- online softmax; denominator is UNMASKED, numerator uses mask ----
        #pragma unroll
        for (int i = 0; i < 4; i++) {
            float mloc = s[i][0];
            #pragma unroll
            for (int j = 1; j < 8; j++) mloc = fmaxf(mloc, s[i][j]);
            mloc = fmaxf(mloc, __shfl_xor_sync(0xffffffffu, mloc, 1));
            mloc = fmaxf(mloc, __shfl_xor_sync(0xffffffffu, mloc, 2));
            mloc = fmaxf(mloc, __shfl_xor_sync(0xffffffffu, mloc, 4));

            float mnew = fmaxf(m_i[i], mloc);
            float alpha = __expf(m_i[i] - mnew);   // exp(-inf)=0 on first tile
            m_i[i] = mnew;

            float lsum = 0.f;
            #pragma unroll
            for (int j = 0; j < 8; j++) {
                float p = __expf(s[i][j] - mnew);
                s[i][j] = p;
                lsum += p;
            }
            lsum += __shfl_xor_sync(0xffffffffu, lsum, 1);
            lsum += __shfl_xor_sync(0xffffffffu, lsum, 2);
            lsum += __shfl_xor_sync(0xffffffffu, lsum, 4);
            l_i[i] = l_i[i] * alpha + lsum;

            #pragma unroll
            for (int j = 0; j < 8; j++) acc[i][j] *= alpha;

            // store masked probabilities for the PV matmul (scattered cols, <=2-way)
            #pragma unroll
            for (int j = 0; j < 8; j++)
                sP[(tr + 16 * i) * STRIDE + tc + 8 * j] = s[i][j] * kmv[j];
        }
        __syncthreads();

        // ---- acc += P_masked @ V  (contiguous d cols: d0 = tc*8) ----
        const int col0 = tc * 8;
        #pragma unroll 2
        for (int kk = 0; kk < BN; kk += 4) {
            float4 pv[4];
            #pragma unroll
            for (int i = 0; i < 4; i++)
                pv[i] = *(const float4*)&sP[(tr + 16 * i) * STRIDE + kk];       // lanes: gap-1 rows -> CF
            #pragma unroll
            for (int u = 0; u < 4; u++) {
                const float4 va  = *(const float4*)&sV[(kk + u) * STRIDE + col0];      // same-row distinct c4 -> CF
                const float4 vb4 = *(const float4*)&sV[(kk + u) * STRIDE + col0 + 4];
                #pragma unroll
                for (int i = 0; i < 4; i++) {
                    const float p = ((const float*)&pv[i])[u];
                    acc[i][0] = fmaf(p, va.x,  acc[i][0]);
                    acc[i][1] = fmaf(p, va.y,  acc[i][1]);
                    acc[i][2] = fmaf(p, va.z,  acc[i][2]);
                    acc[i][3] = fmaf(p, va.w,  acc[i][3]);
                    acc[i][4] = fmaf(p, vb4.x, acc[i][4]);
                    acc[i][5] = fmaf(p, vb4.y, acc[i][5]);
                    acc[i][6] = fmaf(p, vb4.z, acc[i][6]);
                    acc[i][7] = fmaf(p, vb4.w, acc[i][7]);
                }
            }
        }
    }

    // ---- epilogue: divide by unmasked denominator, write out ----
    const int col0 = tc * 8;
    #pragma unroll
    for (int i = 0; i < 4; i++) {
        const float inv = 1.f / l_i[i];
        float4 o1, o2;
        o1.x = acc[i][0] * inv; o1.y = acc[i][1] * inv;
        o1.z = acc[i][2] * inv; o1.w = acc[i][3] * inv;
        o2.x = acc[i][4] * inv; o2.y = acc[i][5] * inv;
        o2.z = acc[i][6] * inv; o2.w = acc[i][7] * inv;
        *(float4*)&ob[(tr + 16 * i) * Dd + col0]     = o1;
        *(float4*)&ob[(tr + 16 * i) * Dd + col0 + 4] = o2;
    }
}

extern "C" void kernel_launch(void* const* d_in, const int* in_sizes, int n_in,
                              void* d_out, int out_size)
{
    const float* q  = (const float*)d_in[0];  // [B,H,S,D]
    const float* k  = (const float*)d_in[1];  // [B,H,S,D]
    const float* v  = (const float*)d_in[2];  // [B,H,S,D]
    // d_in[3] = query_mask (all ones, unused by reference math)
    const float* km = (const float*)d_in[4];  // [B,1,1,S]
    const float* sf = (const float*)d_in[5];  // [B,1,1,1]
    float* out = (float*)d_out;

    cudaFuncSetAttribute(attn_kernel,
                         cudaFuncAttributeMaxDynamicSharedMemorySize, SMEM_BYTES);

    dim3 grid(Ss / BM, Bb * Hh);   // 32 x 32
    attn_kernel<<<grid, NTHREADS, SMEM_BYTES>>>(q, k, v, km, sf, out);
}

// round 7
// speedup vs baseline: 7.5419x; 2.6340x over previous
#include <cuda_runtime.h>
#include <cuda_bf16.h>
#include <stdint.h>
#include <math.h>

#define Bb 2
#define Hh 16
#define Ss 2048
#define Dd 64
#define BM 128          // q rows per CTA (32 per warp)
#define BN 64           // keys per tile
#define NTH 128
#define NKT (Ss / BN)   // 32

// SMEM: bf16 tiles with 144-byte row stride (72 bf16) -> conflict-free ldmatrix
#define RS 144
#define SM_QHI 0
#define SM_QLO (SM_QHI + BM * RS)      // 18432
#define SM_KHI (SM_QLO + BM * RS)      // 36864
#define SM_KLO (SM_KHI + BN * RS)      // 46080
#define SM_VHI (SM_KLO + BN * RS)      // 55296
#define SM_VLO (SM_VHI + BN * RS)      // 64512
#define SM_MASK (SM_VLO + BN * RS)     // 73728
#define SMEM_TOTAL (SM_MASK + BN * 4)  // 73984

__device__ __forceinline__ uint32_t smem_u32(const void* p) {
    uint32_t a;
    asm("{ .reg .u64 t; cvta.to.shared.u64 t, %1; cvt.u32.u64 %0, t; }" : "=r"(a) : "l"(p));
    return a;
}
__device__ __forceinline__ void ldsm4(uint32_t* r, uint32_t a) {
    asm volatile("ldmatrix.sync.aligned.m8n8.x4.shared.b16 {%0,%1,%2,%3}, [%4];"
        : "=r"(r[0]), "=r"(r[1]), "=r"(r[2]), "=r"(r[3]) : "r"(a));
}
__device__ __forceinline__ void ldsm2(uint32_t* r, uint32_t a) {
    asm volatile("ldmatrix.sync.aligned.m8n8.x2.shared.b16 {%0,%1}, [%2];"
        : "=r"(r[0]), "=r"(r[1]) : "r"(a));
}
__device__ __forceinline__ void ldsm2t(uint32_t* r, uint32_t a) {
    asm volatile("ldmatrix.sync.aligned.m8n8.x2.trans.shared.b16 {%0,%1}, [%2];"
        : "=r"(r[0]), "=r"(r[1]) : "r"(a));
}
__device__ __forceinline__ void mma16816(float* d, const uint32_t* a, const uint32_t* b) {
    asm volatile("mma.sync.aligned.m16n8k16.row.col.f32.bf16.bf16.f32 "
        "{%0,%1,%2,%3}, {%4,%5,%6,%7}, {%8,%9}, {%0,%1,%2,%3};"
        : "+f"(d[0]), "+f"(d[1]), "+f"(d[2]), "+f"(d[3])
        : "r"(a[0]), "r"(a[1]), "r"(a[2]), "r"(a[3]), "r"(b[0]), "r"(b[1]));
}
__device__ __forceinline__ uint32_t pack2(float a, float b) {
    uint16_t la = __bfloat16_as_ushort(__float2bfloat16_rn(a));
    uint16_t lb = __bfloat16_as_ushort(__float2bfloat16_rn(b));
    return (uint32_t)la | ((uint32_t)lb << 16);
}
__device__ __forceinline__ float btrunc(float a) { return __bfloat162float(__float2bfloat16_rn(a)); }
__device__ __forceinline__ void split_store(char* hi, char* lo, uint32_t off, float4 v) {
    float hx = btrunc(v.x), hy = btrunc(v.y), hz = btrunc(v.z), hw = btrunc(v.w);
    *(uint2*)(hi + off) = make_uint2(pack2(hx, hy), pack2(hz, hw));
    *(uint2*)(lo + off) = make_uint2(pack2(v.x - hx, v.y - hy), pack2(v.z - hz, v.w - hw));
}

__global__ __launch_bounds__(NTH) void attn_mma(
    const float* __restrict__ q, const float* __restrict__ k,
    const float* __restrict__ v, const float* __restrict__ key_mask,
    const float* __restrict__ scale_factor, float* __restrict__ out)
{
    extern __shared__ char smem[];
    const int tid = threadIdx.x;
    const int w   = tid >> 5;
    const int lane = tid & 31;

    const int qt = blockIdx.x, bh = blockIdx.y, b = bh / Hh;
    const float scale = scale_factor[b];
    const float* km = key_mask + (size_t)b * Ss;
    const float* qb = q + ((size_t)bh * Ss + (size_t)qt * BM) * Dd;
    const float* kb = k + (size_t)bh * Ss * Dd;
    const float* vb = v + (size_t)bh * Ss * Dd;
    float* ob = out + ((size_t)bh * Ss + (size_t)qt * BM) * Dd;
    float* sMask = (float*)(smem + SM_MASK);

    // Q tile: scale + bf16 hi/lo split into smem (resident all tiles)
    for (int i = tid; i < BM * 16; i += NTH) {
        int r = i >> 4, c = i & 15;
        float4 val = ((const float4*)qb)[i];
        val.x *= scale; val.y *= scale; val.z *= scale; val.w *= scale;
        split_store(smem + SM_QHI, smem + SM_QLO, r * RS + c * 8, val);
    }

    // ldmatrix base addresses (per-lane)
    const uint32_t sbase = smem_u32(smem);
    const uint32_t qaH = sbase + SM_QHI + (w * 32 + (lane & 15)) * RS + (lane >> 4) * 16;
    const uint32_t qaL = qaH + (SM_QLO - SM_QHI);
    const uint32_t kaH = sbase + SM_KHI + (lane & 7) * RS + ((lane >> 3) & 1) * 16;
    const uint32_t kaL = kaH + (SM_KLO - SM_KHI);
    const uint32_t vaH = sbase + SM_VHI + (lane & 15) * RS;
    const uint32_t vaL = vaH + (SM_VLO - SM_VHI);

    float oacc[2][8][4];   // [m-tile][d-tile][frag]
    float m_i[2][2], l_i[2][2];
    #pragma unroll
    for (int mt = 0; mt < 2; mt++) {
        m_i[mt][0] = m_i[mt][1] = -INFINITY;
        l_i[mt][0] = l_i[mt][1] = 0.f;
        #pragma unroll
        for (int dt = 0; dt < 8; dt++)
            #pragma unroll
            for (int r = 0; r < 4; r++) oacc[mt][dt][r] = 0.f;
    }

    for (int kt = 0; kt < NKT; kt++) {
        __syncthreads();   // previous tile's smem reads done (no-op cost on kt=0)
        const float* kp = kb + (size_t)kt * BN * Dd;
        const float* vp = vb + (size_t)kt * BN * Dd;
        for (int i = tid; i < BN * 16; i += NTH) {
            int r = i >> 4, c = i & 15;
            uint32_t off = r * RS + c * 8;
            split_store(smem + SM_KHI, smem + SM_KLO, off, ((const float4*)kp)[i]);
            split_store(smem + SM_VHI, smem + SM_VLO, off, ((const float4*)vp)[i]);
        }
        if (tid < 16) *(float4*)&sMask[tid * 4] = ((const float4*)(km + kt * BN))[tid];
        __syncthreads();

        // ================= S = Qsplit @ Ksplit^T =================
        float sacc[2][8][4];
        #pragma unroll
        for (int mt = 0; mt < 2; mt++)
            #pragma unroll
            for (int nt = 0; nt < 8; nt++)
                #pragma unroll
                for (int r = 0; r < 4; r++) sacc[mt][nt][r] = 0.f;

        #pragma unroll
        for (int kc = 0; kc < 4; kc++) {
            uint32_t aH[2][4], aL[2][4];
            #pragma unroll
            for (int mt = 0; mt < 2; mt++) {
                ldsm4(aH[mt], qaH + mt * 16 * RS + kc * 32);
                ldsm4(aL[mt], qaL + mt * 16 * RS + kc * 32);
            }
            #pragma unroll
            for (int nt = 0; nt < 8; nt++) {
                uint32_t bH[2], bL[2];
                ldsm2(bH, kaH + nt * 8 * RS + kc * 32);
                ldsm2(bL, kaL + nt * 8 * RS + kc * 32);
                #pragma unroll
                for (int mt = 0; mt < 2; mt++) {
                    mma16816(sacc[mt][nt], aH[mt], bH);
                    mma16816(sacc[mt][nt], aL[mt], bH);
                    mma16816(sacc[mt][nt], aH[mt], bL);
                }
            }
        }

        // ================= online softmax (per row-slot) =================
        // slot (mt,h): rows w*32 + mt*16 + h*8 + lane/4 ; regs 2h,2h+1 ; cols nt*8+2*(lane&3)+{0,1}
        #pragma unroll
        for (int mt = 0; mt < 2; mt++) {
            #pragma unroll
            for (int h = 0; h < 2; h++) {
                float mold = m_i[mt][h];
                float mx = mold;
                #pragma unroll
                for (int nt = 0; nt < 8; nt++)
                    mx = fmaxf(mx, fmaxf(sacc[mt][nt][2 * h], sacc[mt][nt][2 * h + 1]));
                mx = fmaxf(mx, __shfl_xor_sync(0xffffffffu, mx, 1));
                mx = fmaxf(mx, __shfl_xor_sync(0xffffffffu, mx, 2));
                const float alpha = __expf(mold - mx);   // 0 on first tile
                m_i[mt][h] = mx;

                float ls = 0.f;
                #pragma unroll
                for (int nt = 0; nt < 8; nt++) {
                    float p0 = __expf(sacc[mt][nt][2 * h]     - mx);
                    float p1 = __expf(sacc[mt][nt][2 * h + 1] - mx);
                    ls += p0 + p1;                                        // UNMASKED denom
                    const float2 mk = *(const float2*)&sMask[nt * 8 + 2 * (lane & 3)];
                    sacc[mt][nt][2 * h]     = p0 * mk.x;                  // masked numerator
                    sacc[mt][nt][2 * h + 1] = p1 * mk.y;
                }
                ls += __shfl_xor_sync(0xffffffffu, ls, 1);
                ls += __shfl_xor_sync(0xffffffffu, ls, 2);
                l_i[mt][h] = l_i[mt][h] * alpha + ls;

                #pragma unroll
                for (int dt = 0; dt < 8; dt++) {
                    oacc[mt][dt][2 * h]     *= alpha;
                    oacc[mt][dt][2 * h + 1] *= alpha;
                }
            }
        }

        // ================= O += Psplit @ Vsplit =================
        // P accum regs repack directly into m16k16 A fragments (no smem round trip)
        #pragma unroll
        for (int kc = 0; kc < 4; kc++) {
            uint32_t pH[2][4], pL[2][4];
            #pragma unroll
            for (int mt = 0; mt < 2; mt++) {
                const float* s0 = sacc[mt][2 * kc];
                const float* s1 = sacc[mt][2 * kc + 1];
                float h00 = btrunc(s0[0]), h01 = btrunc(s0[1]), h02 = btrunc(s0[2]), h03 = btrunc(s0[3]);
                float h10 = btrunc(s1[0]), h11 = btrunc(s1[1]), h12 = btrunc(s1[2]), h13 = btrunc(s1[3]);
                pH[mt][0] = pack2(h00, h01); pH[mt][1] = pack2(h02, h03);
                pH[mt][2] = pack2(h10, h11); pH[mt][3] = pack2(h12, h13);
                pL[mt][0] = pack2(s0[0] - h00, s0[1] - h01); pL[mt][1] = pack2(s0[2] - h02, s0[3] - h03);
                pL[mt][2] = pack2(s1[0] - h10, s1[1] - h11); pL[mt][3] = pack2(s1[2] - h12, s1[3] - h13);
            }
            #pragma unroll
            for (int dt = 0; dt < 8; dt++) {
                uint32_t bH[2], bL[2];
                ldsm2t(bH, vaH + kc * 16 * RS + dt * 16);
                ldsm2t(bL, vaL + kc * 16 * RS + dt * 16);
                #pragma unroll
                for (int mt = 0; mt < 2; mt++) {
                    mma16816(oacc[mt][dt], pH[mt], bH);
                    mma16816(oacc[mt][dt], pL[mt], bH);
                    mma16816(oacc[mt][dt], pH[mt], bL);
                }
            }
        }
    }

    // ================= epilogue =================
    #pragma unroll
    for (int mt = 0; mt < 2; mt++) {
        #pragma unroll
        for (int h = 0; h < 2; h++) {
            const float inv = 1.f / l_i[mt][h];
            const int row = w * 32 + mt * 16 + h * 8 + (lane >> 2);
            #pragma unroll
            for (int dt = 0; dt < 8; dt++) {
                float2 o;
                o.x = oacc[mt][dt][2 * h]     * inv;
                o.y = oacc[mt][dt][2 * h + 1] * inv;
                *(float2*)&ob[(size_t)row * Dd + dt * 8 + 2 * (lane & 3)] = o;
            }
        }
    }
}

extern "C" void kernel_launch(void* const* d_in, const int* in_sizes, int n_in,
                              void* d_out, int out_size)
{
    const float* q  = (const float*)d_in[0];
    const float* k  = (const float*)d_in[1];
    const float* v  = (const float*)d_in[2];
    const float* km = (const float*)d_in[4];  // key_mask [B,1,1,S]
    const float* sf = (const float*)d_in[5];  // scale_factor [B]
    float* out = (float*)d_out;

    cudaFuncSetAttribute(attn_mma, cudaFuncAttributeMaxDynamicSharedMemorySize, SMEM_TOTAL);
    dim3 grid(Ss / BM, Bb * Hh);   // 16 x 32
    attn_mma<<<grid, NTH, SMEM_TOTAL>>>(q, k, v, km, sf, out);
}

// round 8
// speedup vs baseline: 8.0371x; 1.0657x over previous
#include <cuda_runtime.h>
#include <cuda_bf16.h>
#include <stdint.h>
#include <math.h>

#define Bb 2
#define Hh 16
#define Ss 2048
#define Dd 64
#define BM 128          // q rows per CTA (16 per warp, 8 warps)
#define BN 64           // keys per tile
#define NTH 256
#define NKT (Ss / BN)   // 32

// SMEM: bf16 tiles with 144-byte row stride (72 bf16) -> conflict-free ldmatrix
#define RS 144
#define SM_QHI 0
#define SM_QLO (SM_QHI + BM * RS)      // 18432
#define SM_KHI (SM_QLO + BM * RS)      // 36864
#define SM_KLO (SM_KHI + BN * RS)      // 46080
#define SM_VHI (SM_KLO + BN * RS)      // 55296
#define SM_VLO (SM_VHI + BN * RS)      // 64512
#define SM_MASK (SM_VLO + BN * RS)     // 73728
#define SMEM_TOTAL (SM_MASK + BN * 4)  // 73984

__device__ __forceinline__ uint32_t smem_u32(const void* p) {
    uint32_t a;
    asm("{ .reg .u64 t; cvta.to.shared.u64 t, %1; cvt.u32.u64 %0, t; }" : "=r"(a) : "l"(p));
    return a;
}
__device__ __forceinline__ void ldsm4(uint32_t* r, uint32_t a) {
    asm volatile("ldmatrix.sync.aligned.m8n8.x4.shared.b16 {%0,%1,%2,%3}, [%4];"
        : "=r"(r[0]), "=r"(r[1]), "=r"(r[2]), "=r"(r[3]) : "r"(a));
}
__device__ __forceinline__ void ldsm2(uint32_t* r, uint32_t a) {
    asm volatile("ldmatrix.sync.aligned.m8n8.x2.shared.b16 {%0,%1}, [%2];"
        : "=r"(r[0]), "=r"(r[1]) : "r"(a));
}
__device__ __forceinline__ void ldsm2t(uint32_t* r, uint32_t a) {
    asm volatile("ldmatrix.sync.aligned.m8n8.x2.trans.shared.b16 {%0,%1}, [%2];"
        : "=r"(r[0]), "=r"(r[1]) : "r"(a));
}
__device__ __forceinline__ void mma16816(float* d, const uint32_t* a, const uint32_t* b) {
    asm volatile("mma.sync.aligned.m16n8k16.row.col.f32.bf16.bf16.f32 "
        "{%0,%1,%2,%3}, {%4,%5,%6,%7}, {%8,%9}, {%0,%1,%2,%3};"
        : "+f"(d[0]), "+f"(d[1]), "+f"(d[2]), "+f"(d[3])
        : "r"(a[0]), "r"(a[1]), "r"(a[2]), "r"(a[3]), "r"(b[0]), "r"(b[1]));
}
__device__ __forceinline__ uint32_t pack2(float a, float b) {
    uint16_t la = __bfloat16_as_ushort(__float2bfloat16_rn(a));
    uint16_t lb = __bfloat16_as_ushort(__float2bfloat16_rn(b));
    return (uint32_t)la | ((uint32_t)lb << 16);
}
__device__ __forceinline__ float btrunc(float a) { return __bfloat162float(__float2bfloat16_rn(a)); }
__device__ __forceinline__ void split_store(char* hi, char* lo, uint32_t off, float4 v) {
    float hx = btrunc(v.x), hy = btrunc(v.y), hz = btrunc(v.z), hw = btrunc(v.w);
    *(uint2*)(hi + off) = make_uint2(pack2(hx, hy), pack2(hz, hw));
    *(uint2*)(lo + off) = make_uint2(pack2(v.x - hx, v.y - hy), pack2(v.z - hz, v.w - hw));
}

__global__ __launch_bounds__(NTH, 2) void attn_mma(
    const float* __restrict__ q, const float* __restrict__ k,
    const float* __restrict__ v, const float* __restrict__ key_mask,
    const float* __restrict__ scale_factor, float* __restrict__ out)
{
    extern __shared__ char smem[];
    const int tid = threadIdx.x;
    const int w   = tid >> 5;       // 0..7, warp owns rows w*16..w*16+15
    const int lane = tid & 31;

    const int qt = blockIdx.x, bh = blockIdx.y, b = bh / Hh;
    const float scale = scale_factor[b] * 1.4426950408889634f;   // fold log2(e): use exp2
    const float* km = key_mask + (size_t)b * Ss;
    const float* qb = q + ((size_t)bh * Ss + (size_t)qt * BM) * Dd;
    const float* kb = k + (size_t)bh * Ss * Dd;
    const float* vb = v + (size_t)bh * Ss * Dd;
    float* ob = out + ((size_t)bh * Ss + (size_t)qt * BM) * Dd;
    float* sMask = (float*)(smem + SM_MASK);

    // Q tile: scale + bf16 hi/lo split into smem (resident all tiles)
    for (int i = tid; i < BM * 16; i += NTH) {
        int r = i >> 4, c = i & 15;
        float4 val = ((const float4*)qb)[i];
        val.x *= scale; val.y *= scale; val.z *= scale; val.w *= scale;
        split_store(smem + SM_QHI, smem + SM_QLO, r * RS + c * 8, val);
    }

    // ldmatrix base addresses (per-lane)
    const uint32_t sbase = smem_u32(smem);
    const uint32_t qaH = sbase + SM_QHI + (w * 16 + (lane & 15)) * RS + (lane >> 4) * 16;
    const uint32_t qaL = qaH + (SM_QLO - SM_QHI);
    const uint32_t kaH = sbase + SM_KHI + (lane & 7) * RS + ((lane >> 3) & 1) * 16;
    const uint32_t kaL = kaH + (SM_KLO - SM_KHI);
    const uint32_t vaH = sbase + SM_VHI + (lane & 15) * RS;
    const uint32_t vaL = vaH + (SM_VLO - SM_VHI);

    float oacc[8][4];       // [d-tile][frag]
    float m_i[2], l_i[2];
    m_i[0] = m_i[1] = -INFINITY;
    l_i[0] = l_i[1] = 0.f;
    #pragma unroll
    for (int dt = 0; dt < 8; dt++)
        #pragma unroll
        for (int r = 0; r < 4; r++) oacc[dt][r] = 0.f;

    for (int kt = 0; kt < NKT; kt++) {
        __syncthreads();   // previous tile's smem reads done
        const float* kp = kb + (size_t)kt * BN * Dd;
        const float* vp = vb + (size_t)kt * BN * Dd;
        for (int i = tid; i < BN * 16; i += NTH) {
            int r = i >> 4, c = i & 15;
            uint32_t off = r * RS + c * 8;
            split_store(smem + SM_KHI, smem + SM_KLO, off, ((const float4*)kp)[i]);
            split_store(smem + SM_VHI, smem + SM_VLO, off, ((const float4*)vp)[i]);
        }
        if (tid < 16) *(float4*)&sMask[tid * 4] = ((const float4*)(km + kt * BN))[tid];
        __syncthreads();

        // ================= S = Qsplit @ Ksplit^T =================
        float sacc[8][4];
        #pragma unroll
        for (int nt = 0; nt < 8; nt++)
            #pragma unroll
            for (int r = 0; r < 4; r++) sacc[nt][r] = 0.f;

        #pragma unroll
        for (int kc = 0; kc < 4; kc++) {
            uint32_t aH[4], aL[4];
            ldsm4(aH, qaH + kc * 32);
            ldsm4(aL, qaL + kc * 32);
            #pragma unroll
            for (int nt = 0; nt < 8; nt++) {
                uint32_t bH[2], bL[2];
                ldsm2(bH, kaH + nt * 8 * RS + kc * 32);
                ldsm2(bL, kaL + nt * 8 * RS + kc * 32);
                mma16816(sacc[nt], aH, bH);
                mma16816(sacc[nt], aL, bH);
                mma16816(sacc[nt], aH, bL);
            }
        }

        // ================= online softmax (base-2; per row-slot h) =================
        // slot h: row w*16 + h*8 + lane/4 ; regs 2h,2h+1 ; cols nt*8+2*(lane&3)+{0,1}
        #pragma unroll
        for (int h = 0; h < 2; h++) {
            float mold = m_i[h];
            float mx = mold;
            #pragma unroll
            for (int nt = 0; nt < 8; nt++)
                mx = fmaxf(mx, fmaxf(sacc[nt][2 * h], sacc[nt][2 * h + 1]));
            mx = fmaxf(mx, __shfl_xor_sync(0xffffffffu, mx, 1));
            mx = fmaxf(mx, __shfl_xor_sync(0xffffffffu, mx, 2));
            const float alpha = exp2f(mold - mx);   // 0 on first tile
            m_i[h] = mx;

            float ls = 0.f;
            #pragma unroll
            for (int nt = 0; nt < 8; nt++) {
                float p0 = exp2f(sacc[nt][2 * h]     - mx);
                float p1 = exp2f(sacc[nt][2 * h + 1] - mx);
                ls += p0 + p1;                                        // UNMASKED denom
                const float2 mk = *(const float2*)&sMask[nt * 8 + 2 * (lane & 3)];
                sacc[nt][2 * h]     = p0 * mk.x;                      // masked numerator
                sacc[nt][2 * h + 1] = p1 * mk.y;
            }
            ls += __shfl_xor_sync(0xffffffffu, ls, 1);
            ls += __shfl_xor_sync(0xffffffffu, ls, 2);
            l_i[h] = l_i[h] * alpha + ls;

            #pragma unroll
            for (int dt = 0; dt < 8; dt++) {
                oacc[dt][2 * h]     *= alpha;
                oacc[dt][2 * h + 1] *= alpha;
            }
        }

        // ================= O += Psplit @ Vsplit =================
        #pragma unroll
        for (int kc = 0; kc < 4; kc++) {
            uint32_t pH[4], pL[4];
            {
                const float* s0 = sacc[2 * kc];
                const float* s1 = sacc[2 * kc + 1];
                float h00 = btrunc(s0[0]), h01 = btrunc(s0[1]), h02 = btrunc(s0[2]), h03 = btrunc(s0[3]);
                float h10 = btrunc(s1[0]), h11 = btrunc(s1[1]), h12 = btrunc(s1[2]), h13 = btrunc(s1[3]);
                pH[0] = pack2(h00, h01); pH[1] = pack2(h02, h03);
                pH[2] = pack2(h10, h11); pH[3] = pack2(h12, h13);
                pL[0] = pack2(s0[0] - h00, s0[1] - h01); pL[1] = pack2(s0[2] - h02, s0[3] - h03);
                pL[2] = pack2(s1[0] - h10, s1[1] - h11); pL[3] = pack2(s1[2] - h12, s1[3] - h13);
            }
            #pragma unroll
            for (int dt = 0; dt < 8; dt++) {
                uint32_t bH[2], bL[2];
                ldsm2t(bH, vaH + kc * 16 * RS + dt * 16);
                ldsm2t(bL, vaL + kc * 16 * RS + dt * 16);
                mma16816(oacc[dt], pH, bH);
                mma16816(oacc[dt], pL, bH);
                mma16816(oacc[dt], pH, bL);
            }
        }
    }

    // ================= epilogue =================
    #pragma unroll
    for (int h = 0; h < 2; h++) {
        const float inv = 1.f / l_i[h];
        const int row = w * 16 + h * 8 + (lane >> 2);
        #pragma unroll
        for (int dt = 0; dt < 8; dt++) {
            float2 o;
            o.x = oacc[dt][2 * h]     * inv;
            o.y = oacc[dt][2 * h + 1] * inv;
            *(float2*)&ob[(size_t)row * Dd + dt * 8 + 2 * (lane & 3)] = o;
        }
    }
}

extern "C" void kernel_launch(void* const* d_in, const int* in_sizes, int n_in,
                              void* d_out, int out_size)
{
    const float* q  = (const float*)d_in[0];
    const float* k  = (const float*)d_in[1];
    const float* v  = (const float*)d_in[2];
    const float* km = (const float*)d_in[4];  // key_mask [B,1,1,S]
    const float* sf = (const float*)d_in[5];  // scale_factor [B]
    float* out = (float*)d_out;

    cudaFuncSetAttribute(attn_mma, cudaFuncAttributeMaxDynamicSharedMemorySize, SMEM_TOTAL);
    dim3 grid(Ss / BM, Bb * Hh);   // 16 x 32
    attn_mma<<<grid, NTH, SMEM_TOTAL>>>(q, k, v, km, sf, out);
}

// round 10
// speedup vs baseline: 10.4258x; 1.2972x over previous
#include <cuda_runtime.h>
#include <cuda_bf16.h>
#include <stdint.h>
#include <math.h>

#define Bb 2
#define Hh 16
#define Ss 2048
#define Dd 64
#define BM 128          // q rows per CTA (16 per warp, 8 warps)
#define BN 64           // keys per tile
#define NTH 256
#define NKT (Ss / BN)   // 32

// SMEM layout (bytes). bf16 tiles use 144-byte row stride -> conflict-free ldmatrix.
#define RS 144
#define SM_QHI 0
#define SM_QLO (SM_QHI + BM * RS)       // 18432
#define SM_KHI (SM_QLO + BM * RS)       // 36864
#define SM_KLO (SM_KHI + BN * RS)       // 46080
#define SM_VHI (SM_KLO + BN * RS)       // 55296
#define SM_VLO (SM_VHI + BN * RS)       // 64512
#define SM_MASK (SM_VLO + BN * RS)      // 73728: 2 bufs x 64 floats
#define SM_STGK (SM_MASK + 512)         // 74240: fp32 K staging 16384
#define SM_STGV (SM_STGK + BN * Dd * 4) // 90624: fp32 V staging 16384
#define SMEM_TOTAL (SM_STGV + BN * Dd * 4)  // 107008 -> 2 CTAs/SM

__device__ __forceinline__ uint32_t smem_u32(const void* p) {
    uint32_t a;
    asm("{ .reg .u64 t; cvta.to.shared.u64 t, %1; cvt.u32.u64 %0, t; }" : "=r"(a) : "l"(p));
    return a;
}
#define CP16(dst, src) asm volatile("cp.async.cg.shared.global [%0], [%1], 16;" :: "r"(dst), "l"(src))
#define CP_COMMIT()    asm volatile("cp.async.commit_group;" ::: "memory")
#define CP_WAIT0()     asm volatile("cp.async.wait_group 0;" ::: "memory")

__device__ __forceinline__ void ldsm4(uint32_t* r, uint32_t a) {
    asm volatile("ldmatrix.sync.aligned.m8n8.x4.shared.b16 {%0,%1,%2,%3}, [%4];"
        : "=r"(r[0]), "=r"(r[1]), "=r"(r[2]), "=r"(r[3]) : "r"(a));
}
__device__ __forceinline__ void ldsm4t(uint32_t* r, uint32_t a) {
    asm volatile("ldmatrix.sync.aligned.m8n8.x4.trans.shared.b16 {%0,%1,%2,%3}, [%4];"
        : "=r"(r[0]), "=r"(r[1]), "=r"(r[2]), "=r"(r[3]) : "r"(a));
}
__device__ __forceinline__ void mma16816(float* d, const uint32_t* a, const uint32_t* b) {
    asm volatile("mma.sync.aligned.m16n8k16.row.col.f32.bf16.bf16.f32 "
        "{%0,%1,%2,%3}, {%4,%5,%6,%7}, {%8,%9}, {%0,%1,%2,%3};"
        : "+f"(d[0]), "+f"(d[1]), "+f"(d[2]), "+f"(d[3])
        : "r"(a[0]), "r"(a[1]), "r"(a[2]), "r"(a[3]), "r"(b[0]), "r"(b[1]));
}
// pack two f32 into bf16x2 (a -> low half, memory order)
__device__ __forceinline__ uint32_t cvtbf2(float a, float b) {
    uint32_t r;
    asm("cvt.rn.bf16x2.f32 %0, %1, %2;" : "=r"(r) : "f"(b), "f"(a));
    return r;
}
// hi/lo split of a float4 into two bf16x2-pair stores; bf16->f32 recovery is an exact shift
__device__ __forceinline__ void split_store(char* hi, char* lo, uint32_t off, float4 v) {
    uint32_t h01 = cvtbf2(v.x, v.y), h23 = cvtbf2(v.z, v.w);
    float hx = __uint_as_float(h01 << 16);
    float hy = __uint_as_float(h01 & 0xffff0000u);
    float hz = __uint_as_float(h23 << 16);
    float hw = __uint_as_float(h23 & 0xffff0000u);
    *(uint2*)(hi + off) = make_uint2(h01, h23);
    *(uint2*)(lo + off) = make_uint2(cvtbf2(v.x - hx, v.y - hy), cvtbf2(v.z - hz, v.w - hw));
}

__global__ __launch_bounds__(NTH, 2) void attn_mma(
    const float* __restrict__ q, const float* __restrict__ k,
    const float* __restrict__ v, const float* __restrict__ key_mask,
    const float* __restrict__ scale_factor, float* __restrict__ out)
{
    extern __shared__ char smem[];
    const int tid = threadIdx.x;
    const int w   = tid >> 5;       // warp owns rows w*16..w*16+15
    const int lane = tid & 31;

    const int qt = blockIdx.x, bh = blockIdx.y, b = bh / Hh;
    const float scale = scale_factor[b] * 1.4426950408889634f;   // fold log2(e); use exp2
    const float* km = key_mask + (size_t)b * Ss;
    const float* qb = q + ((size_t)bh * Ss + (size_t)qt * BM) * Dd;
    const float* kb = k + (size_t)bh * Ss * Dd;
    const float* vb = v + (size_t)bh * Ss * Dd;
    float* ob = out + ((size_t)bh * Ss + (size_t)qt * BM) * Dd;
    float* sMask = (float*)(smem + SM_MASK);
    const uint32_t sbase = smem_u32(smem);

    // ---- prologue: stage tile 0 via cp.async (overlaps Q conversion below) ----
    for (int i = tid; i < BN * 16; i += NTH) {
        CP16(sbase + SM_STGK + i * 16, (const char*)kb + i * 16);
        CP16(sbase + SM_STGV + i * 16, (const char*)vb + i * 16);
    }
    if (tid < 16) CP16(sbase + SM_MASK + tid * 16, (const char*)km + tid * 16);
    CP_COMMIT();

    // Q tile: scale + bf16 hi/lo split into smem (resident all tiles)
    for (int i = tid; i < BM * 16; i += NTH) {
        int r = i >> 4, c = i & 15;
        float4 val = ((const float4*)qb)[i];
        val.x *= scale; val.y *= scale; val.z *= scale; val.w *= scale;
        split_store(smem + SM_QHI, smem + SM_QLO, r * RS + c * 8, val);
    }

    CP_WAIT0();
    __syncthreads();
    // convert tile 0: staging fp32 -> bf16 hi/lo
    for (int i = tid; i < BN * 16; i += NTH) {
        int r = i >> 4, c = i & 15;
        uint32_t off = r * RS + c * 8;
        split_store(smem + SM_KHI, smem + SM_KLO, off, *(const float4*)(smem + SM_STGK + i * 16));
        split_store(smem + SM_VHI, smem + SM_VLO, off, *(const float4*)(smem + SM_STGV + i * 16));
    }
    __syncthreads();

    // ldmatrix base addresses (per-lane)
    const uint32_t qaH = sbase + SM_QHI + (w * 16 + (lane & 15)) * RS + (lane >> 4) * 16;
    const uint32_t qaL = qaH + (SM_QLO - SM_QHI);
    // K x4: lanes 0-7 keys(lane&7) k-lo | 8-15 k-hi | 16-23 keys+8 k-lo | 24-31 keys+8 k-hi
    const uint32_t kaH = sbase + SM_KHI + ((lane & 7) + ((lane >> 4) << 3)) * RS + (((lane >> 3) & 1) << 4);
    const uint32_t kaL = kaH + (SM_KLO - SM_KHI);
    // V x4 trans: lanes 0-15 rows, d-cols dt | 16-31 same rows, d-cols dt+1
    const uint32_t vaH = sbase + SM_VHI + (lane & 15) * RS + ((lane >> 4) << 4);
    const uint32_t vaL = vaH + (SM_VLO - SM_VHI);

    float oacc[8][4];
    float m_i[2], l_i[2];
    m_i[0] = m_i[1] = -INFINITY;
    l_i[0] = l_i[1] = 0.f;
    #pragma unroll
    for (int dt = 0; dt < 8; dt++)
        #pragma unroll
        for (int r = 0; r < 4; r++) oacc[dt][r] = 0.f;

    for (int kt = 0; kt < NKT; kt++) {
        // ---- stage tile kt+1 (register-free; hidden behind compute) ----
        if (kt + 1 < NKT) {
            const char* kp = (const char*)(kb + (size_t)(kt + 1) * BN * Dd);
            const char* vp = (const char*)(vb + (size_t)(kt + 1) * BN * Dd);
            for (int i = tid; i < BN * 16; i += NTH) {
                CP16(sbase + SM_STGK + i * 16, kp + i * 16);
                CP16(sbase + SM_STGV + i * 16, vp + i * 16);
            }
            if (tid < 16)
                CP16(sbase + SM_MASK + ((kt + 1) & 1) * 256 + tid * 16,
                     (const char*)(km + (kt + 1) * BN) + tid * 16);
            CP_COMMIT();
        }
        const float* mk_tile = sMask + (kt & 1) * 64;

        // ================= S = Qsplit @ Ksplit^T =================
        float sacc[8][4];
        #pragma unroll
        for (int nt = 0; nt < 8; nt++)
            #pragma unroll
            for (int r = 0; r < 4; r++) sacc[nt][r] = 0.f;

        #pragma unroll
        for (int kc = 0; kc < 4; kc++) {
            uint32_t aH[4], aL[4];
            ldsm4(aH, qaH + kc * 32);
            ldsm4(aL, qaL + kc * 32);
            #pragma unroll
            for (int nt = 0; nt < 8; nt += 2) {
                uint32_t bH[4], bL[4];
                ldsm4(bH, kaH + nt * 8 * RS + kc * 32);
                ldsm4(bL, kaL + nt * 8 * RS + kc * 32);
                mma16816(sacc[nt], aH, bH);
                mma16816(sacc[nt], aL, bH);
                mma16816(sacc[nt], aH, bL);
                mma16816(sacc[nt + 1], aH, bH + 2);
                mma16816(sacc[nt + 1], aL, bH + 2);
                mma16816(sacc[nt + 1], aH, bL + 2);
            }
        }

        // ================= online softmax (base-2, per row-slot h) =================
        #pragma unroll
        for (int h = 0; h < 2; h++) {
            float mold = m_i[h];
            float mx = mold;
            #pragma unroll
            for (int nt = 0; nt < 8; nt++)
                mx = fmaxf(mx, fmaxf(sacc[nt][2 * h], sacc[nt][2 * h + 1]));
            mx = fmaxf(mx, __shfl_xor_sync(0xffffffffu, mx, 1));
            mx = fmaxf(mx, __shfl_xor_sync(0xffffffffu, mx, 2));
            const float alpha = exp2f(mold - mx);   // 0 on first tile
            m_i[h] = mx;

            float ls = 0.f;
            #pragma unroll
            for (int nt = 0; nt < 8; nt++) {
                float p0 = exp2f(sacc[nt][2 * h]     - mx);
                float p1 = exp2f(sacc[nt][2 * h + 1] - mx);
                ls += p0 + p1;                                        // UNMASKED denominator
                const float2 mk = *(const float2*)&mk_tile[nt * 8 + 2 * (lane & 3)];
                sacc[nt][2 * h]     = p0 * mk.x;                      // masked numerator
                sacc[nt][2 * h + 1] = p1 * mk.y;
            }
            ls += __shfl_xor_sync(0xffffffffu, ls, 1);
            ls += __shfl_xor_sync(0xffffffffu, ls, 2);
            l_i[h] = l_i[h] * alpha + ls;

            #pragma unroll
            for (int dt = 0; dt < 8; dt++) {
                oacc[dt][2 * h]     *= alpha;
                oacc[dt][2 * h + 1] *= alpha;
            }
        }

        // ================= O += Psplit @ Vsplit =================
        #pragma unroll
        for (int kc = 0; kc < 4; kc++) {
            uint32_t pH[4], pL[4];
            {
                const float* s0 = sacc[2 * kc];
                const float* s1 = sacc[2 * kc + 1];
                pH[0] = cvtbf2(s0[0], s0[1]); pH[1] = cvtbf2(s0[2], s0[3]);
                pH[2] = cvtbf2(s1[0], s1[1]); pH[3] = cvtbf2(s1[2], s1[3]);
                float a0 = __uint_as_float(pH[0] << 16), a1 = __uint_as_float(pH[0] & 0xffff0000u);
                float a2 = __uint_as_float(pH[1] << 16), a3 = __uint_as_float(pH[1] & 0xffff0000u);
                float b0 = __uint_as_float(pH[2] << 16), b1 = __uint_as_float(pH[2] & 0xffff0000u);
                float b2 = __uint_as_float(pH[3] << 16), b3 = __uint_as_float(pH[3] & 0xffff0000u);
                pL[0] = cvtbf2(s0[0] - a0, s0[1] - a1); pL[1] = cvtbf2(s0[2] - a2, s0[3] - a3);
                pL[2] = cvtbf2(s1[0] - b0, s1[1] - b1); pL[3] = cvtbf2(s1[2] - b2, s1[3] - b3);
            }
            #pragma unroll
            for (int dt = 0; dt < 8; dt += 2) {
                uint32_t bH[4], bL[4];
                ldsm4t(bH, vaH + kc * 16 * RS + dt * 16);
                ldsm4t(bL, vaL + kc * 16 * RS + dt * 16);
                mma16816(oacc[dt], pH, bH);
                mma16816(oacc[dt], pL, bH);
                mma16816(oacc[dt], pH, bL);
                mma16816(oacc[dt + 1], pH, bH + 2);
                mma16816(oacc[dt + 1], pL, bH + 2);
                mma16816(oacc[dt + 1], pH, bL + 2);
            }
        }

        // ---- convert staged tile kt+1 into bf16 buffers ----
        if (kt + 1 < NKT) {
            CP_WAIT0();
            __syncthreads();           // all warps done reading bf16 bufs + staging landed
            for (int i = tid; i < BN * 16; i += NTH) {
                int r = i >> 4, c = i & 15;
                uint32_t off = r * RS + c * 8;
                split_store(smem + SM_KHI, smem + SM_KLO, off, *(const float4*)(smem + SM_STGK + i * 16));
                split_store(smem + SM_VHI, smem + SM_VLO, off, *(const float4*)(smem + SM_STGV + i * 16));
            }
            __syncthreads();
        }
    }

    // ================= epilogue =================
    #pragma unroll
    for (int h = 0; h < 2; h++) {
        const float inv = 1.f / l_i[h];
        const int row = w * 16 + h * 8 + (lane >> 2);
        #pragma unroll
        for (int dt = 0; dt < 8; dt++) {
            float2 o;
            o.x = oacc[dt][2 * h]     * inv;
            o.y = oacc[dt][2 * h + 1] * inv;
            *(float2*)&ob[(size_t)row * Dd + dt * 8 + 2 * (lane & 3)] = o;
        }
    }
}

extern "C" void kernel_launch(void* const* d_in, const int* in_sizes, int n_in,
                              void* d_out, int out_size)
{
    const float* q  = (const float*)d_in[0];
    const float* k  = (const float*)d_in[1];
    const float* v  = (const float*)d_in[2];
    const float* km = (const float*)d_in[4];  // key_mask [B,1,1,S]
    const float* sf = (const float*)d_in[5];  // scale_factor [B]
    float* out = (float*)d_out;

    cudaFuncSetAttribute(attn_mma, cudaFuncAttributeMaxDynamicSharedMemorySize, SMEM_TOTAL);
    dim3 grid(Ss / BM, Bb * Hh);   // 16 x 32
    attn_mma<<<grid, NTH, SMEM_TOTAL>>>(q, k, v, km, sf, out);
}

// round 13
// speedup vs baseline: 14.2896x; 1.3706x over previous
#include <cuda_runtime.h>
#include <cuda_fp16.h>
#include <stdint.h>
#include <math.h>

#define Bb 2
#define Hh 16
#define Ss 2048
#define Dd 64
#define BM 128          // q rows per CTA (16 per warp, 8 warps)
#define BN 64           // keys per tile
#define NTH 256
#define NKT (Ss / BN)   // 32
#define NELEM (Bb * Hh * Ss * Dd)   // 4194304
#define N4 (NELEM / 4)              // 1048576 float4s; per-batch float4s = 2^19

// Pre-converted operands (device-global scratch; allocation-free per harness rules)
__device__ __half g_qhi[NELEM];
__device__ __half g_qlo[NELEM];
__device__ __half g_khi[NELEM];
__device__ __half g_klo[NELEM];
__device__ __half g_v[NELEM];

// SMEM layout (bytes). fp16 tiles, 144-byte row stride -> conflict-free ldmatrix.
#define RS 144
#define SM_QHI 0
#define SM_QLO (SM_QHI + BM * RS)        // 18432
#define SM_KHI (SM_QLO + BM * RS)        // 36864: 2 bufs x 9216
#define SM_KLO (SM_KHI + 2 * BN * RS)    // 55296: 2 bufs
#define SM_V   (SM_KLO + 2 * BN * RS)    // 73728: 2 bufs
#define SM_MASK (SM_V + 2 * BN * RS)     // 92160: 2 bufs x 256 B
#define SMEM_TOTAL (SM_MASK + 512)       // 92672 -> 2 CTAs/SM

__device__ __forceinline__ uint32_t smem_u32(const void* p) {
    uint32_t a;
    asm("{ .reg .u64 t; cvta.to.shared.u64 t, %1; cvt.u32.u64 %0, t; }" : "=r"(a) : "l"(p));
    return a;
}
#define CP16(dst, src) asm volatile("cp.async.cg.shared.global [%0], [%1], 16;" :: "r"(dst), "l"(src))
#define CP_COMMIT()    asm volatile("cp.async.commit_group;" ::: "memory")
#define CP_WAIT0()     asm volatile("cp.async.wait_group 0;" ::: "memory")

__device__ __forceinline__ void ldsm4(uint32_t* r, uint32_t a) {
    asm volatile("ldmatrix.sync.aligned.m8n8.x4.shared.b16 {%0,%1,%2,%3}, [%4];"
        : "=r"(r[0]), "=r"(r[1]), "=r"(r[2]), "=r"(r[3]) : "r"(a));
}
__device__ __forceinline__ void ldsm4t(uint32_t* r, uint32_t a) {
    asm volatile("ldmatrix.sync.aligned.m8n8.x4.trans.shared.b16 {%0,%1,%2,%3}, [%4];"
        : "=r"(r[0]), "=r"(r[1]), "=r"(r[2]), "=r"(r[3]) : "r"(a));
}
__device__ __forceinline__ void mma16816(float* d, const uint32_t* a, const uint32_t* b) {
    asm volatile("mma.sync.aligned.m16n8k16.row.col.f32.f16.f16.f32 "
        "{%0,%1,%2,%3}, {%4,%5,%6,%7}, {%8,%9}, {%0,%1,%2,%3};"
        : "+f"(d[0]), "+f"(d[1]), "+f"(d[2]), "+f"(d[3])
        : "r"(a[0]), "r"(a[1]), "r"(a[2]), "r"(a[3]), "r"(b[0]), "r"(b[1]));
}
// pack two f32 -> f16x2 (a in low half = memory order)
__device__ __forceinline__ uint32_t cvth2(float a, float b) {
    uint32_t r;
    asm("cvt.rn.f16x2.f32 %0, %1, %2;" : "=r"(r) : "f"(b), "f"(a));
    return r;
}
__device__ __forceinline__ float h2lo(uint32_t h) {
    return __half2float(__ushort_as_half((unsigned short)(h & 0xffffu)));
}
__device__ __forceinline__ float h2hi(uint32_t h) {
    return __half2float(__ushort_as_half((unsigned short)(h >> 16)));
}

// ================= pre-pass: fp32 -> fp16 (hi/lo for Q,K; single for V) =================
__global__ __launch_bounds__(256) void prepass(
    const float* __restrict__ q, const float* __restrict__ k,
    const float* __restrict__ v, const float* __restrict__ sf)
{
    const int idx = blockIdx.x * 256 + threadIdx.x;   // float4 index
    const int job = blockIdx.y;
    if (job == 0) {
        float4 val = ((const float4*)q)[idx];
        const float s = sf[idx >> 19] * 1.4426950408889634f;   // fold log2(e)
        val.x *= s; val.y *= s; val.z *= s; val.w *= s;
        uint32_t h01 = cvth2(val.x, val.y), h23 = cvth2(val.z, val.w);
        uint32_t l01 = cvth2(val.x - h2lo(h01), val.y - h2hi(h01));
        uint32_t l23 = cvth2(val.z - h2lo(h23), val.w - h2hi(h23));
        ((uint2*)g_qhi)[idx] = make_uint2(h01, h23);
        ((uint2*)g_qlo)[idx] = make_uint2(l01, l23);
    } else if (job == 1) {
        float4 val = ((const float4*)k)[idx];
        uint32_t h01 = cvth2(val.x, val.y), h23 = cvth2(val.z, val.w);
        uint32_t l01 = cvth2(val.x - h2lo(h01), val.y - h2hi(h01));
        uint32_t l23 = cvth2(val.z - h2lo(h23), val.w - h2hi(h23));
        ((uint2*)g_khi)[idx] = make_uint2(h01, h23);
        ((uint2*)g_klo)[idx] = make_uint2(l01, l23);
    } else {
        float4 val = ((const float4*)v)[idx];
        ((uint2*)g_v)[idx] = make_uint2(cvth2(val.x, val.y), cvth2(val.z, val.w));
    }
}

// ================= main attention kernel =================
__global__ __launch_bounds__(NTH, 2) void attn_mma(
    const float* __restrict__ key_mask, float* __restrict__ out)
{
    extern __shared__ char smem[];
    const int tid = threadIdx.x;
    const int w   = tid >> 5;       // warp owns rows w*16..w*16+15
    const int lane = tid & 31;

    const int qt = blockIdx.x, bh = blockIdx.y, b = bh / Hh;
    const float* km = key_mask + (size_t)b * Ss;
    const char* qhp = (const char*)(g_qhi + ((size_t)bh * Ss + (size_t)qt * BM) * Dd);
    const char* qlp = (const char*)(g_qlo + ((size_t)bh * Ss + (size_t)qt * BM) * Dd);
    const char* kbh = (const char*)(g_khi + (size_t)bh * Ss * Dd);
    const char* kbl = (const char*)(g_klo + (size_t)bh * Ss * Dd);
    const char* vbp = (const char*)(g_v   + (size_t)bh * Ss * Dd);
    float* ob = out + ((size_t)bh * Ss + (size_t)qt * BM) * Dd;
    float* sMask = (float*)(smem + SM_MASK);
    const uint32_t sbase = smem_u32(smem);

    // ---- prologue: load Q (hi+lo) and tile 0 (K hi/lo, V, mask) via cp.async ----
    for (int i = tid; i < BM * 8; i += NTH) {      // 128 rows x 8 chunks, hi & lo
        int r = i >> 3, c = i & 7;
        uint32_t off = r * RS + c * 16;
        CP16(sbase + SM_QHI + off, qhp + i * 16);
        CP16(sbase + SM_QLO + off, qlp + i * 16);
    }
    for (int i = tid; i < BN * 8; i += NTH) {      // 64 rows x 8 chunks
        int r = i >> 3, c = i & 7;
        uint32_t off = r * RS + c * 16;
        CP16(sbase + SM_KHI + off, kbh + i * 16);
        CP16(sbase + SM_KLO + off, kbl + i * 16);
        CP16(sbase + SM_V   + off, vbp + i * 16);
    }
    if (tid < 16) CP16(sbase + SM_MASK + tid * 16, (const char*)km + tid * 16);
    CP_COMMIT();
    CP_WAIT0();
    __syncthreads();

    // ldmatrix base addresses (per-lane), buf-0 variants
    const uint32_t qaH = sbase + SM_QHI + (w * 16 + (lane & 15)) * RS + (lane >> 4) * 16;
    const uint32_t qaL = qaH + (SM_QLO - SM_QHI);
    const uint32_t ka0 = ((lane & 7) + ((lane >> 4) << 3)) * RS + (((lane >> 3) & 1) << 4);
    const uint32_t va0 = (lane & 15) * RS + ((lane >> 4) << 4);

    float oacc[8][4];
    float m_i[2], l_i[2];
    m_i[0] = m_i[1] = -INFINITY;
    l_i[0] = l_i[1] = 0.f;
    #pragma unroll
    for (int dt = 0; dt < 8; dt++)
        #pragma unroll
        for (int r = 0; r < 4; r++) oacc[dt][r] = 0.f;

    for (int kt = 0; kt < NKT; kt++) {
        const int buf = kt & 1;
        // ---- prefetch tile kt+1 into the other buffer ----
        if (kt + 1 < NKT) {
            const size_t toff = (size_t)(kt + 1) * BN * Dd * 2;   // bytes (fp16)
            const uint32_t bo = (buf ^ 1) * BN * RS;
            for (int i = tid; i < BN * 8; i += NTH) {
                int r = i >> 3, c = i & 7;
                uint32_t off = bo + r * RS + c * 16;
                CP16(sbase + SM_KHI + off, kbh + toff + i * 16);
                CP16(sbase + SM_KLO + off, kbl + toff + i * 16);
                CP16(sbase + SM_V   + off, vbp + toff + i * 16);
            }
            if (tid < 16)
                CP16(sbase + SM_MASK + (buf ^ 1) * 256 + tid * 16,
                     (const char*)(km + (kt + 1) * BN) + tid * 16);
            CP_COMMIT();
        }
        const float* mk_tile = sMask + buf * 64;
        const uint32_t kaH = sbase + SM_KHI + buf * BN * RS + ka0;
        const uint32_t kaL = sbase + SM_KLO + buf * BN * RS + ka0;
        const uint32_t vaB = sbase + SM_V   + buf * BN * RS + va0;

        // ================= S = Qsplit @ Ksplit^T (3-term fp16 split) =================
        float sacc[8][4];
        #pragma unroll
        for (int nt = 0; nt < 8; nt++)
            #pragma unroll
            for (int r = 0; r < 4; r++) sacc[nt][r] = 0.f;

        #pragma unroll
        for (int kc = 0; kc < 4; kc++) {
            uint32_t aH[4], aL[4];
            ldsm4(aH, qaH + kc * 32);
            ldsm4(aL, qaL + kc * 32);
            #pragma unroll
            for (int nt = 0; nt < 8; nt += 2) {
                uint32_t bH[4], bL[4];
                ldsm4(bH, kaH + nt * 8 * RS + kc * 32);
                ldsm4(bL, kaL + nt * 8 * RS + kc * 32);
                mma16816(sacc[nt],     aH, bH);
                mma16816(sacc[nt + 1], aH, bH + 2);
                mma16816(sacc[nt],     aL, bH);
                mma16816(sacc[nt + 1], aL, bH + 2);
                mma16816(sacc[nt],     aH, bL);
                mma16816(sacc[nt + 1], aH, bL + 2);
            }
        }

        // ================= online softmax (base-2, per row-slot h) =================
        #pragma unroll
        for (int h = 0; h < 2; h++) {
            float mold = m_i[h];
            float mx = mold;
            #pragma unroll
            for (int nt = 0; nt < 8; nt++)
                mx = fmaxf(mx, fmaxf(sacc[nt][2 * h], sacc[nt][2 * h + 1]));
            mx = fmaxf(mx, __shfl_xor_sync(0xffffffffu, mx, 1));
            mx = fmaxf(mx, __shfl_xor_sync(0xffffffffu, mx, 2));
            const float alpha = exp2f(mold - mx);   // 0 on first tile
            m_i[h] = mx;

            float ls = 0.f;
            #pragma unroll
            for (int nt = 0; nt < 8; nt++) {
                float p0 = exp2f(sacc[nt][2 * h]     - mx);
                float p1 = exp2f(sacc[nt][2 * h + 1] - mx);
                ls += p0 + p1;                                        // UNMASKED denominator
                const float2 mk = *(const float2*)&mk_tile[nt * 8 + 2 * (lane & 3)];
                sacc[nt][2 * h]     = p0 * mk.x;                      // masked numerator
                sacc[nt][2 * h + 1] = p1 * mk.y;
            }
            ls += __shfl_xor_sync(0xffffffffu, ls, 1);
            ls += __shfl_xor_sync(0xffffffffu, ls, 2);
            l_i[h] = l_i[h] * alpha + ls;

            #pragma unroll
            for (int dt = 0; dt < 8; dt++) {
                oacc[dt][2 * h]     *= alpha;
                oacc[dt][2 * h + 1] *= alpha;
            }
        }

        // ================= O += P(fp16) @ V(fp16) =================
        #pragma unroll
        for (int kc = 0; kc < 4; kc++) {
            uint32_t pP[4];
            {
                const float* s0 = sacc[2 * kc];
                const float* s1 = sacc[2 * kc + 1];
                pP[0] = cvth2(s0[0], s0[1]); pP[1] = cvth2(s0[2], s0[3]);
                pP[2] = cvth2(s1[0], s1[1]); pP[3] = cvth2(s1[2], s1[3]);
            }
            #pragma unroll
            for (int dt = 0; dt < 8; dt += 2) {
                uint32_t bV[4];
                ldsm4t(bV, vaB + kc * 16 * RS + dt * 16);
                mma16816(oacc[dt],     pP, bV);
                mma16816(oacc[dt + 1], pP, bV + 2);
            }
        }

        // ---- make prefetched tile visible to all threads ----
        if (kt + 1 < NKT) {
            CP_WAIT0();
            __syncthreads();
        }
    }

    // ================= epilogue =================
    #pragma unroll
    for (int h = 0; h < 2; h++) {
        const float inv = 1.f / l_i[h];
        const int row = w * 16 + h * 8 + (lane >> 2);
        #pragma unroll
        for (int dt = 0; dt < 8; dt++) {
            float2 o;
            o.x = oacc[dt][2 * h]     * inv;
            o.y = oacc[dt][2 * h + 1] * inv;
            *(float2*)&ob[(size_t)row * Dd + dt * 8 + 2 * (lane & 3)] = o;
        }
    }
}

extern "C" void kernel_launch(void* const* d_in, const int* in_sizes, int n_in,
                              void* d_out, int out_size)
{
    const float* q  = (const float*)d_in[0];
    const float* k  = (const float*)d_in[1];
    const float* v  = (const float*)d_in[2];
    const float* km = (const float*)d_in[4];  // key_mask [B,1,1,S]
    const float* sf = (const float*)d_in[5];  // scale_factor [B]
    float* out = (float*)d_out;

    dim3 pgrid(N4 / 256, 3);
    prepass<<<pgrid, 256>>>(q, k, v, sf);

    cudaFuncSetAttribute(attn_mma, cudaFuncAttributeMaxDynamicSharedMemorySize, SMEM_TOTAL);
    dim3 grid(Ss / BM, Bb * Hh);   // 16 x 32
    attn_mma<<<grid, NTH, SMEM_TOTAL>>>(km, out);
}